// round 11
// baseline (speedup 1.0000x reference)
#include <cuda_runtime.h>
#include <cstdint>

#define NCLS   10
#define NTHR   256
#define WARPS  8
#define NBLK   592    // 4 CTAs/SM x 148 SMs (45KB smem/CTA)
#define G      256    // float4-groups per tile (12KB/stage across 3 arrays)
#define STG    2

__device__ float g_sum[NCLS];
__device__ float g_cnt[NCLS];
__device__ unsigned int g_done;   // zero-initialized; reset by finalizing block

struct SmemLayout {
    float4 st_o[STG][G];
    float4 st_t[STG][G];
    int4   st_m[STG][G];
    float2 acc[WARPS][NCLS][32];
    float  s_le[NCLS];
    unsigned int s_last;
    unsigned long long mbar[STG] __attribute__((aligned(8)));
};

__device__ __forceinline__ uint32_t smem_u32(const void* p) {
    uint32_t a;
    asm("{ .reg .u64 t; cvta.to.shared.u64 t, %1; cvt.u32.u64 %0, t; }"
        : "=r"(a) : "l"(p));
    return a;
}

__device__ __forceinline__ void mbar_init(uint32_t addr, uint32_t cnt) {
    asm volatile("mbarrier.init.shared.b64 [%0], %1;" :: "r"(addr), "r"(cnt) : "memory");
}

__device__ __forceinline__ void mbar_expect_tx(uint32_t addr, uint32_t bytes) {
    asm volatile("mbarrier.arrive.expect_tx.shared.b64 _, [%0], %1;"
                 :: "r"(addr), "r"(bytes) : "memory");
}

__device__ __forceinline__ void mbar_wait(uint32_t addr, uint32_t phase) {
    asm volatile(
        "{\n\t"
        ".reg .pred P;\n\t"
        "WAIT_%=:\n\t"
        "mbarrier.try_wait.parity.acquire.cta.shared::cta.b64 P, [%0], %1, 0x989680;\n\t"
        "@P bra.uni DONE_%=;\n\t"
        "bra.uni WAIT_%=;\n\t"
        "DONE_%=:\n\t"
        "}"
        :: "r"(addr), "r"(phase) : "memory");
}

__device__ __forceinline__ void bulk_g2s(uint32_t dst, const void* src,
                                         uint32_t bytes, uint32_t mbar) {
    asm volatile(
        "cp.async.bulk.shared::cta.global.mbarrier::complete_tx::bytes [%0], [%1], %2, [%3];"
        :: "r"(dst), "l"(src), "r"(bytes), "r"(mbar) : "memory");
}

__device__ __forceinline__ void acc1(float o, float t, int m, float2* lane_base) {
    float d  = o - t;
    float mf = (float)m;
    int   c  = (int)t;
    float dm = d * mf;
    float2 v = lane_base[c * 32];
    v.x = fmaf(d, dm, v.x);
    v.y += mf;
    lane_base[c * 32] = v;
}

__global__ __launch_bounds__(NTHR) void loss_kernel(
    const float4* __restrict__ o4,
    const float4* __restrict__ t4,
    const int4*   __restrict__ m4,
    const float*  __restrict__ o_s,
    const float*  __restrict__ t_s,
    const int*    __restrict__ m_s,
    float* __restrict__ out,
    int n4, int n, int out_size)
{
    __shared__ SmemLayout sm;

    int tid = threadIdx.x;
    int w = tid >> 5, l = tid & 31;

    // Zero hist accumulators (word index 2*lane mod 32 -> conflict-free RMW).
    #pragma unroll
    for (int c = 0; c < NCLS; ++c) sm.acc[w][c][l] = make_float2(0.f, 0.f);
    if (tid == 0) {
        mbar_init(smem_u32(&sm.mbar[0]), 1);
        mbar_init(smem_u32(&sm.mbar[1]), 1);
    }
    __syncthreads();

    float2* lane_base = &sm.acc[w][0][l];   // class stride = 32 float2
    int ntiles = (n4 + G - 1) / G;

    // Producer helper state (thread 0 only issues bulks).
    uint32_t mb[STG] = { smem_u32(&sm.mbar[0]), smem_u32(&sm.mbar[1]) };
    uint32_t dst_o[STG] = { smem_u32(&sm.st_o[0][0]), smem_u32(&sm.st_o[1][0]) };
    uint32_t dst_t[STG] = { smem_u32(&sm.st_t[0][0]), smem_u32(&sm.st_t[1][0]) };
    uint32_t dst_m[STG] = { smem_u32(&sm.st_m[0][0]), smem_u32(&sm.st_m[1][0]) };

    // Prologue: load first tile into stage 0.
    int t0 = blockIdx.x;
    if (tid == 0 && t0 < ntiles) {
        uint32_t gc = (uint32_t)min(G, n4 - t0 * G);
        uint32_t bytes = gc * 16u;
        mbar_expect_tx(mb[0], bytes * 3u);
        bulk_g2s(dst_o[0], o4 + (size_t)t0 * G, bytes, mb[0]);
        bulk_g2s(dst_t[0], t4 + (size_t)t0 * G, bytes, mb[0]);
        bulk_g2s(dst_m[0], m4 + (size_t)t0 * G, bytes, mb[0]);
    }

    int k = 0;
    for (int t = t0; t < ntiles; t += gridDim.x, ++k) {
        int s = k & 1;

        // Issue NEXT tile into the other stage (it was fully consumed and
        // __syncthreads-drained at iteration k-1).
        int tn = t + gridDim.x;
        if (tid == 0 && tn < ntiles) {
            int sn = s ^ 1;
            uint32_t gc = (uint32_t)min(G, n4 - tn * G);
            uint32_t bytes = gc * 16u;
            mbar_expect_tx(mb[sn], bytes * 3u);
            bulk_g2s(dst_o[sn], o4 + (size_t)tn * G, bytes, mb[sn]);
            bulk_g2s(dst_t[sn], t4 + (size_t)tn * G, bytes, mb[sn]);
            bulk_g2s(dst_m[sn], m4 + (size_t)tn * G, bytes, mb[sn]);
        }

        // Wait for current tile. Stage s's use-count is k/2 -> phase (k/2)&1.
        mbar_wait(mb[s], (uint32_t)((k >> 1) & 1));

        // Each thread consumes exactly its own float4 triple.
        if (t * G + tid < n4) {
            float4 o = sm.st_o[s][tid];
            float4 tt = sm.st_t[s][tid];
            int4   m = sm.st_m[s][tid];
            acc1(o.x, tt.x, m.x, lane_base);
            acc1(o.y, tt.y, m.y, lane_base);
            acc1(o.z, tt.z, m.z, lane_base);
            acc1(o.w, tt.w, m.w, lane_base);
        }
        __syncthreads();   // stage s fully consumed before reuse at k+2
    }

    // Scalar tail (defensive; n = 16.78M divisible by 4 so normally empty).
    if (blockIdx.x == 0) {
        for (int kk = n4 * 4 + tid; kk < n; kk += NTHR)
            acc1(o_s[kk], t_s[kk], m_s[kk], lane_base);
    }

    __syncthreads();

    // Block reduction: 320 slots (cls, lane); lane dim reduces via shfl in-warp.
    for (int s2 = tid; s2 < NCLS * 32; s2 += NTHR) {
        int c = s2 >> 5, ll = s2 & 31;
        float sum = 0.f, cnt = 0.f;
        #pragma unroll
        for (int ww = 0; ww < WARPS; ++ww) {
            float2 v = sm.acc[ww][c][ll];
            sum += v.x; cnt += v.y;
        }
        #pragma unroll
        for (int off = 16; off; off >>= 1) {
            sum += __shfl_down_sync(0xffffffffu, sum, off);
            cnt += __shfl_down_sync(0xffffffffu, cnt, off);
        }
        if (ll == 0) {
            atomicAdd(&g_sum[c], sum);
            atomicAdd(&g_cnt[c], cnt);
        }
    }

    // Last-block-done finalize (single launch; graph-replay safe via reset).
    __threadfence();
    __syncthreads();
    if (tid == 0)
        sm.s_last = (atomicAdd(&g_done, 1u) == (unsigned)gridDim.x - 1u) ? 1u : 0u;
    __syncthreads();

    if (sm.s_last) {
        if (tid < NCLS) {
            float s = g_sum[tid], nn = g_cnt[tid];
            float v = (nn > 0.f) ? s / fmaxf(nn, 1.f) : 0.f;
            sm.s_le[tid] = v;
            if (1 + tid  < out_size) out[1 + tid]  = v;   // loss_each
            if (11 + tid < out_size) out[11 + tid] = nn;  // class_n
            g_sum[tid] = 0.f;   // reset for next graph replay
            g_cnt[tid] = 0.f;
        }
        __syncthreads();
        if (tid == 0) {
            float loss = 0.f;
            #pragma unroll
            for (int c = 0; c < NCLS; ++c) loss += 0.1f * sm.s_le[c];
            if (out_size > 0) out[0] = loss;
            g_done = 0u;
        }
        for (int kk = 21 + tid; kk < out_size; kk += NTHR) out[kk] = 0.f;
    }
}

extern "C" void kernel_launch(void* const* d_in, const int* in_sizes, int n_in,
                              void* d_out, int out_size) {
    const float* outputs = (const float*)d_in[0];
    const float* targets = (const float*)d_in[1];
    const int*   mask    = (const int*)d_in[2];
    int n  = in_sizes[0];
    int n4 = n >> 2;

    loss_kernel<<<NBLK, NTHR>>>(
        (const float4*)outputs, (const float4*)targets, (const int4*)mask,
        outputs, targets, mask, (float*)d_out, n4, n, out_size);
}

// round 12
// speedup vs baseline: 1.0365x; 1.0365x over previous
#include <cuda_runtime.h>

#define NCLS   10
#define NTHR   256
#define WARPS  8
#define NBLK   888   // uniform 6 CTAs/SM x 148 = measured-best 48 warps/SM

__device__ float g_sum[NCLS];
__device__ float g_cnt[NCLS];
__device__ unsigned int g_done;   // zero-initialized; reset by finalizing block

__device__ __forceinline__ void acc1(float o, float t, int m, float2* lane_base) {
    float d  = o - t;
    float mf = (float)m;
    int   c  = (int)t;
    float dm = d * mf;
    float2 v = lane_base[c * 32];
    v.x = fmaf(d, dm, v.x);
    v.y += mf;
    lane_base[c * 32] = v;
}

__device__ __forceinline__ void acc4(const float4& o, const float4& t, const int4& m,
                                     float2* lane_base) {
    acc1(o.x, t.x, m.x, lane_base);
    acc1(o.y, t.y, m.y, lane_base);
    acc1(o.z, t.z, m.z, lane_base);
    acc1(o.w, t.w, m.w, lane_base);
}

__global__ __launch_bounds__(NTHR) void loss_kernel(
    const float4* __restrict__ o4,
    const float4* __restrict__ t4,
    const int4*   __restrict__ m4,
    const float*  __restrict__ o_s,
    const float*  __restrict__ t_s,
    const int*    __restrict__ m_s,
    float* __restrict__ out,
    int n4, int n, int out_size)
{
    // Per-warp, per-lane-column accumulators: acc[warp][cls][lane] = (sum, cnt).
    // Lane owns its column -> plain RMW, no atomics. Word index =
    // 2*lane mod 32 -> conflict-free per half-warp phase.
    __shared__ float2 acc[WARPS][NCLS][32];
    __shared__ float s_le[NCLS];
    __shared__ unsigned int s_last;

    int tid = threadIdx.x;
    int w = tid >> 5, l = tid & 31;

    #pragma unroll
    for (int c = 0; c < NCLS; ++c) acc[w][c][l] = make_float2(0.f, 0.f);
    __syncthreads();

    float2* lane_base = &acc[w][0][l];   // class stride = 32 float2

    int idx    = blockIdx.x * NTHR + tid;
    int stride = gridDim.x * NTHR;

    // Register prefetch pipeline + __ldcs (evict-first: data is stream-once,
    // reuse distance 201MB >> 126MB L2 -> normal allocation only adds
    // eviction/tag work). Load-path alternatives (TMA bulk, deeper batching,
    // more/fewer warps) all measured at the same ~4.7TB/s plateau (R4-R11).
    int i = idx;
    if (i < n4) {
        float4 o = __ldcs(&o4[i]);
        float4 t = __ldcs(&t4[i]);
        int4   m = __ldcs(&m4[i]);
        for (; i + stride < n4; i += stride) {
            float4 o2 = __ldcs(&o4[i + stride]);
            float4 t2 = __ldcs(&t4[i + stride]);
            int4   m2 = __ldcs(&m4[i + stride]);
            acc4(o, t, m, lane_base);
            o = o2; t = t2; m = m2;
        }
        acc4(o, t, m, lane_base);   // drain last prefetched iter
    }

    // Scalar tail (defensive; n = 16.78M divisible by 4 so normally empty).
    if (blockIdx.x == 0) {
        for (int k = n4 * 4 + tid; k < n; k += NTHR)
            acc1(o_s[k], t_s[k], m_s[k], lane_base);
    }

    __syncthreads();

    // Block reduction: 320 slots (cls, lane); lane dim reduces via shfl in-warp.
    for (int s = tid; s < NCLS * 32; s += NTHR) {
        int c = s >> 5, ll = s & 31;
        float sum = 0.f, cnt = 0.f;
        #pragma unroll
        for (int ww = 0; ww < WARPS; ++ww) {
            float2 v = acc[ww][c][ll];
            sum += v.x; cnt += v.y;
        }
        #pragma unroll
        for (int off = 16; off; off >>= 1) {
            sum += __shfl_down_sync(0xffffffffu, sum, off);
            cnt += __shfl_down_sync(0xffffffffu, cnt, off);
        }
        if (ll == 0) {
            atomicAdd(&g_sum[c], sum);
            atomicAdd(&g_cnt[c], cnt);
        }
    }

    // Last-block-done finalize (single launch; graph-replay safe via reset).
    __threadfence();
    __syncthreads();
    if (tid == 0)
        s_last = (atomicAdd(&g_done, 1u) == (unsigned)gridDim.x - 1u) ? 1u : 0u;
    __syncthreads();

    if (s_last) {
        if (tid < NCLS) {
            float s = g_sum[tid], nn = g_cnt[tid];
            float v = (nn > 0.f) ? s / fmaxf(nn, 1.f) : 0.f;
            s_le[tid] = v;
            if (1 + tid  < out_size) out[1 + tid]  = v;   // loss_each
            if (11 + tid < out_size) out[11 + tid] = nn;  // class_n
            // Reset for next graph replay (restores zero-initialized state).
            g_sum[tid] = 0.f;
            g_cnt[tid] = 0.f;
        }
        __syncthreads();
        if (tid == 0) {
            float loss = 0.f;
            #pragma unroll
            for (int c = 0; c < NCLS; ++c) loss += 0.1f * s_le[c];
            if (out_size > 0) out[0] = loss;
            g_done = 0u;
        }
        // Zero any tail beyond the 21 expected outputs (d_out is poisoned).
        for (int k = 21 + tid; k < out_size; k += NTHR) out[k] = 0.f;
    }
}

extern "C" void kernel_launch(void* const* d_in, const int* in_sizes, int n_in,
                              void* d_out, int out_size) {
    const float* outputs = (const float*)d_in[0];
    const float* targets = (const float*)d_in[1];
    const int*   mask    = (const int*)d_in[2];
    int n  = in_sizes[0];
    int n4 = n >> 2;

    loss_kernel<<<NBLK, NTHR>>>(
        (const float4*)outputs, (const float4*)targets, (const int4*)mask,
        outputs, targets, mask, (float*)d_out, n4, n, out_size);
}